// round 1
// baseline (speedup 1.0000x reference)
#include <cuda_runtime.h>
#include <cuda_bf16.h>
#include <math.h>

#define U_DIM 6000
#define I_DIM 3072
#define B_DIM 3000
#define EMB 64
#define HEADS 8
#define BATCH 4096
#define UB_DIM 9000   // U + B

// ---------------------------------------------------------------------------
// Scratch (no allocations allowed -> __device__ globals)
// ---------------------------------------------------------------------------
// layout (floats):
//  it0    : 3072*64
//  q,k,v  : 3*3072*64
//  ctx    : 3072*64
//  items  : 3072*64
//  P      : 3000*64   relu(bi_avg @ items)
//  b1     : 3000*64
//  fub0   : 9000*64   [users_f ; bundles_f]
//  tbuf   : 9000*64   fub0 @ W_ub
//  fub    : 9000*64
//  allub  : 9000*192
__device__ float g_scratch[5019648];

#define OFF_IT0    0
#define OFF_Q      196608
#define OFF_K      393216
#define OFF_V      589824
#define OFF_CTX    786432
#define OFF_ITEMS  983040
#define OFF_P      1179648
#define OFF_B1     1371648
#define OFF_FUB0   1563648
#define OFF_T      2139648
#define OFF_FUB    2715648
#define OFF_ALLUB  3291648

// ---------------------------------------------------------------------------
// Warp-scan SpMM: out = relu(G1row.X1 + bias) [+ relu(G2row.X2)] [+ add]
// optional out2 = relu(G1row.X1 + bias)
// Warp per row, lanes own cols (lane, lane+32). float4 scan + ballot skip.
// ---------------------------------------------------------------------------
__device__ __forceinline__ void scan_sub(unsigned m, float v, int base4, int sub,
                                         const float* __restrict__ X, int lane,
                                         float& a0, float& a1)
{
    while (m) {
        int j = __ffs(m) - 1;
        m &= m - 1;
        float val = __shfl_sync(0xffffffffu, v, j);
        const float* xr = X + (size_t)((base4 + j) * 4 + sub) * 64;
        a0 = fmaf(val, xr[lane], a0);
        a1 = fmaf(val, xr[lane + 32], a1);
    }
}

__device__ __forceinline__ void scan_row(const float* __restrict__ G, int K,
                                         const float* __restrict__ X,
                                         int row, int lane, float& a0, float& a1)
{
    const float4* g4 = reinterpret_cast<const float4*>(G + (size_t)row * K);
    int nf4 = K >> 2;  // all K here are multiples of 4
    for (int base = 0; base < nf4; base += 32) {
        int idx = base + lane;
        float4 v = make_float4(0.f, 0.f, 0.f, 0.f);
        if (idx < nf4) v = __ldg(g4 + idx);
        unsigned ma = __ballot_sync(0xffffffffu, v.x != 0.f);
        unsigned mb = __ballot_sync(0xffffffffu, v.y != 0.f);
        unsigned mc = __ballot_sync(0xffffffffu, v.z != 0.f);
        unsigned md = __ballot_sync(0xffffffffu, v.w != 0.f);
        scan_sub(ma, v.x, base, 0, X, lane, a0, a1);
        scan_sub(mb, v.y, base, 1, X, lane, a0, a1);
        scan_sub(mc, v.z, base, 2, X, lane, a0, a1);
        scan_sub(md, v.w, base, 3, X, lane, a0, a1);
    }
}

__global__ void scan_spmm_kernel(const float* __restrict__ G1, int K1,
                                 const float* __restrict__ X1,
                                 const float* __restrict__ G2, int K2,
                                 const float* __restrict__ X2,
                                 const float* __restrict__ addv,
                                 const float* __restrict__ bias,
                                 float* __restrict__ out,
                                 float* __restrict__ out2, int R)
{
    int row = (int)((blockIdx.x * blockDim.x + threadIdx.x) >> 5);
    if (row >= R) return;
    int lane = threadIdx.x & 31;

    float a0 = 0.f, a1 = 0.f;
    scan_row(G1, K1, X1, row, lane, a0, a1);
    float r0 = a0 + (bias ? bias[lane] : 0.f);
    float r1 = a1 + (bias ? bias[lane + 32] : 0.f);
    r0 = fmaxf(r0, 0.f);
    r1 = fmaxf(r1, 0.f);
    if (out2) {
        out2[(size_t)row * 64 + lane] = r0;
        out2[(size_t)row * 64 + lane + 32] = r1;
    }
    float o0 = r0, o1 = r1;
    if (G2) {
        float b0 = 0.f, b1v = 0.f;
        scan_row(G2, K2, X2, row, lane, b0, b1v);
        o0 += fmaxf(b0, 0.f);
        o1 += fmaxf(b1v, 0.f);
    }
    if (addv) {
        o0 += addv[(size_t)row * 64 + lane];
        o1 += addv[(size_t)row * 64 + lane + 32];
    }
    out[(size_t)row * 64 + lane] = o0;
    out[(size_t)row * 64 + lane + 32] = o1;
}

// ---------------------------------------------------------------------------
// QKV projection: q = (X@Wq)/sqrt(8), k = X@Wk, v = X@Wv
// ---------------------------------------------------------------------------
__global__ void qkv_kernel(const float* __restrict__ X,
                           const float* __restrict__ Wq,
                           const float* __restrict__ Wk,
                           const float* __restrict__ Wv,
                           float* __restrict__ q, float* __restrict__ k,
                           float* __restrict__ v, int N)
{
    __shared__ float wq[4096], wk[4096], wv[4096];
    int t = threadIdx.x;
    for (int i = t; i < 4096; i += 256) {
        wq[i] = Wq[i]; wk[i] = Wk[i]; wv[i] = Wv[i];
    }
    __syncthreads();
    int col = t & 63, rl = t >> 6;
    for (int c = 0; c < 32; c += 4) {
        int r = blockIdx.x * 32 + c + rl;
        if (r < N) {
            const float* x = X + (size_t)r * 64;
            float aq = 0.f, ak = 0.f, av = 0.f;
#pragma unroll
            for (int kk = 0; kk < 64; kk++) {
                float xv = __ldg(x + kk);
                aq = fmaf(xv, wq[kk * 64 + col], aq);
                ak = fmaf(xv, wk[kk * 64 + col], ak);
                av = fmaf(xv, wv[kk * 64 + col], av);
            }
            q[(size_t)r * 64 + col] = aq * 0.3535533905932738f; // 1/sqrt(8)
            k[(size_t)r * 64 + col] = ak;
            v[(size_t)r * 64 + col] = av;
        }
    }
}

// ---------------------------------------------------------------------------
// Generic small GEMM: out = X (N x 64) @ W (64 x 64)
// ---------------------------------------------------------------------------
__global__ void gemm64_kernel(const float* __restrict__ X,
                              const float* __restrict__ W,
                              float* __restrict__ out, int N)
{
    __shared__ float ws[4096];
    int t = threadIdx.x;
    for (int i = t; i < 4096; i += 256) ws[i] = W[i];
    __syncthreads();
    int col = t & 63, rl = t >> 6;
    for (int c = 0; c < 32; c += 4) {
        int r = blockIdx.x * 32 + c + rl;
        if (r < N) {
            const float* x = X + (size_t)r * 64;
            float acc = 0.f;
#pragma unroll
            for (int kk = 0; kk < 64; kk++)
                acc = fmaf(__ldg(x + kk), ws[kk * 64 + col], acc);
            out[(size_t)r * 64 + col] = acc;
        }
    }
}

// ---------------------------------------------------------------------------
// Flash attention: 8 heads, dh=8, N=3072. Warp per row, lanes stride m.
// ---------------------------------------------------------------------------
#define AT_CHUNK 512
__global__ void attn_kernel(const float* __restrict__ qg,
                            const float* __restrict__ kg,
                            const float* __restrict__ vg,
                            float* __restrict__ ctx)
{
    __shared__ float4 ks4[AT_CHUNK * 2];
    __shared__ float4 vs4[AT_CHUNK * 2];
    int t = threadIdx.x;
    int warp = t >> 5, lane = t & 31;
    int head = blockIdx.x / 384;          // 3072/8 rows per block => 384 blocks/head
    int rowbase = (blockIdx.x % 384) * 8;
    int n = rowbase + warp;
    int h8 = head * 8;

    float ql[8];
    {
        const float4* qp = reinterpret_cast<const float4*>(qg + (size_t)n * 64 + h8);
        float4 a = qp[0], b = qp[1];
        ql[0] = a.x; ql[1] = a.y; ql[2] = a.z; ql[3] = a.w;
        ql[4] = b.x; ql[5] = b.y; ql[6] = b.z; ql[7] = b.w;
    }

    float mx = -1e30f, sm = 0.f;
    float acc[8];
#pragma unroll
    for (int d = 0; d < 8; d++) acc[d] = 0.f;

    for (int m0 = 0; m0 < I_DIM; m0 += AT_CHUNK) {
        for (int idx = t; idx < AT_CHUNK * 2; idx += 256) {
            int i = idx >> 1, part = idx & 1;
            const float4* kp = reinterpret_cast<const float4*>(
                kg + (size_t)(m0 + i) * 64 + h8 + part * 4);
            const float4* vp = reinterpret_cast<const float4*>(
                vg + (size_t)(m0 + i) * 64 + h8 + part * 4);
            ks4[idx] = *kp;
            vs4[idx] = *vp;
        }
        __syncthreads();
        for (int mm = lane; mm < AT_CHUNK; mm += 32) {
            float4 ka = ks4[mm * 2], kb = ks4[mm * 2 + 1];
            float s = ql[0] * ka.x + ql[1] * ka.y + ql[2] * ka.z + ql[3] * ka.w +
                      ql[4] * kb.x + ql[5] * kb.y + ql[6] * kb.z + ql[7] * kb.w;
            float p;
            if (s > mx) {
                float c = __expf(mx - s);
                sm *= c;
#pragma unroll
                for (int d = 0; d < 8; d++) acc[d] *= c;
                mx = s;
                p = 1.f;
            } else {
                p = __expf(s - mx);
            }
            sm += p;
            float4 va = vs4[mm * 2], vb = vs4[mm * 2 + 1];
            acc[0] = fmaf(p, va.x, acc[0]); acc[1] = fmaf(p, va.y, acc[1]);
            acc[2] = fmaf(p, va.z, acc[2]); acc[3] = fmaf(p, va.w, acc[3]);
            acc[4] = fmaf(p, vb.x, acc[4]); acc[5] = fmaf(p, vb.y, acc[5]);
            acc[6] = fmaf(p, vb.z, acc[6]); acc[7] = fmaf(p, vb.w, acc[7]);
        }
        __syncthreads();
    }

    // merge 32 lane-partials (mx, sm, acc)
    float M = mx;
#pragma unroll
    for (int o = 16; o; o >>= 1) M = fmaxf(M, __shfl_xor_sync(0xffffffffu, M, o));
    float c = __expf(mx - M);
    sm *= c;
#pragma unroll
    for (int d = 0; d < 8; d++) acc[d] *= c;
#pragma unroll
    for (int o = 16; o; o >>= 1) {
        sm += __shfl_xor_sync(0xffffffffu, sm, o);
#pragma unroll
        for (int d = 0; d < 8; d++) acc[d] += __shfl_xor_sync(0xffffffffu, acc[d], o);
    }
    if (lane == 0) {
        float inv = 1.f / sm;
        float* op = ctx + (size_t)n * 64 + h8;
#pragma unroll
        for (int d = 0; d < 8; d++) op[d] = acc[d] * inv;
    }
}

// ---------------------------------------------------------------------------
// Row-wise L2 normalize (64 cols), norm clamped at 1e-12
// ---------------------------------------------------------------------------
__global__ void l2norm_kernel(const float* __restrict__ X, float* __restrict__ out, int R)
{
    int row = (int)((blockIdx.x * blockDim.x + threadIdx.x) >> 5);
    if (row >= R) return;
    int lane = threadIdx.x & 31;
    float v0 = X[(size_t)row * 64 + lane];
    float v1 = X[(size_t)row * 64 + lane + 32];
    float ss = v0 * v0 + v1 * v1;
#pragma unroll
    for (int o = 16; o; o >>= 1) ss += __shfl_xor_sync(0xffffffffu, ss, o);
    float inv = 1.f / fmaxf(sqrtf(ss), 1e-12f);
    out[(size_t)row * 64 + lane] = v0 * inv;
    out[(size_t)row * 64 + lane + 32] = v1 * inv;
}

// ---------------------------------------------------------------------------
// _att2 fusion + all_ub assembly:
// x0 = f_ub0[r]; x1 = (r<U ? f_ub0[r] (users_f) : b1[r-U])
// 2-way softmax over (x0.w, x1.w); fused = a0*x0 + a1*x1
// all_ub[r] = [ f_ub0[r] | l2norm([f_ub[r], fused]) ]  (192 cols)
// ---------------------------------------------------------------------------
__global__ void att2_allub_kernel(const float* __restrict__ f_ub0,
                                  const float* __restrict__ b1,
                                  const float* __restrict__ f_ub,
                                  const float* __restrict__ attw,
                                  float* __restrict__ all_ub)
{
    int row = (int)((blockIdx.x * blockDim.x + threadIdx.x) >> 5);
    if (row >= UB_DIM) return;
    int lane = threadIdx.x & 31;

    float x00 = f_ub0[(size_t)row * 64 + lane];
    float x01 = f_ub0[(size_t)row * 64 + lane + 32];
    float x10, x11;
    if (row < U_DIM) { x10 = x00; x11 = x01; }
    else {
        x10 = b1[(size_t)(row - U_DIM) * 64 + lane];
        x11 = b1[(size_t)(row - U_DIM) * 64 + lane + 32];
    }
    float w0 = attw[lane], w1 = attw[lane + 32];
    float l0 = x00 * w0 + x01 * w1;
    float l1 = x10 * w0 + x11 * w1;
#pragma unroll
    for (int o = 16; o; o >>= 1) {
        l0 += __shfl_xor_sync(0xffffffffu, l0, o);
        l1 += __shfl_xor_sync(0xffffffffu, l1, o);
    }
    float m = fmaxf(l0, l1);
    float e0 = __expf(l0 - m), e1 = __expf(l1 - m);
    float inv = 1.f / (e0 + e1);
    float a0 = e0 * inv, a1 = e1 * inv;
    float fu0 = a0 * x00 + a1 * x10;
    float fu1 = a0 * x01 + a1 * x11;

    float g0 = f_ub[(size_t)row * 64 + lane];
    float g1 = f_ub[(size_t)row * 64 + lane + 32];
    float ss = g0 * g0 + g1 * g1 + fu0 * fu0 + fu1 * fu1;
#pragma unroll
    for (int o = 16; o; o >>= 1) ss += __shfl_xor_sync(0xffffffffu, ss, o);
    float invn = 1.f / fmaxf(sqrtf(ss), 1e-12f);

    size_t ob = (size_t)row * 192;
    all_ub[ob + lane] = x00;
    all_ub[ob + 32 + lane] = x01;
    all_ub[ob + 64 + lane] = g0 * invn;
    all_ub[ob + 96 + lane] = g1 * invn;
    all_ub[ob + 128 + lane] = fu0 * invn;
    all_ub[ob + 160 + lane] = fu1 * invn;
}

// ---------------------------------------------------------------------------
// Final gather + MLP: new_emb = [ue*be | be | ue] (576) -> relu(@p1_W+p1_b) @ p2_W + p2_b
// Warp per batch element.
// ---------------------------------------------------------------------------
__global__ void final_kernel(const float* __restrict__ all_ub,
                             const int* __restrict__ users,
                             const int* __restrict__ bundles,
                             const float* __restrict__ p1W,
                             const float* __restrict__ p1b,
                             const float* __restrict__ p2W,
                             const float* __restrict__ p2b,
                             float* __restrict__ out, int batch)
{
    int b = (int)((blockIdx.x * blockDim.x + threadIdx.x) >> 5);
    if (b >= batch) return;
    int lane = threadIdx.x & 31;
    const float* ue = all_ub + (size_t)users[b] * 192;
    const float* be = all_ub + (size_t)(U_DIM + bundles[b]) * 192;

    float acc[8];
#pragma unroll
    for (int j = 0; j < 8; j++) acc[j] = 0.f;

    for (int i = 0; i < 18; i++) {
        int e0 = lane + 32 * i;  // < 576
        float val;
        if (e0 < 192) val = ue[e0] * be[e0];
        else if (e0 < 384) val = be[e0 - 192];
        else val = ue[e0 - 384];
        const float4* wr = reinterpret_cast<const float4*>(p1W + (size_t)e0 * 8);
        float4 wa = wr[0], wb = wr[1];
        acc[0] = fmaf(val, wa.x, acc[0]); acc[1] = fmaf(val, wa.y, acc[1]);
        acc[2] = fmaf(val, wa.z, acc[2]); acc[3] = fmaf(val, wa.w, acc[3]);
        acc[4] = fmaf(val, wb.x, acc[4]); acc[5] = fmaf(val, wb.y, acc[5]);
        acc[6] = fmaf(val, wb.z, acc[6]); acc[7] = fmaf(val, wb.w, acc[7]);
    }
#pragma unroll
    for (int o = 16; o; o >>= 1) {
#pragma unroll
        for (int j = 0; j < 8; j++)
            acc[j] += __shfl_xor_sync(0xffffffffu, acc[j], o);
    }
    if (lane == 0) {
        float r = p2b[0];
#pragma unroll
        for (int j = 0; j < 8; j++)
            r += fmaxf(acc[j] + p1b[j], 0.f) * p2W[j];
        out[b] = r;
    }
}

// ---------------------------------------------------------------------------
// Launcher
// ---------------------------------------------------------------------------
extern "C" void kernel_launch(void* const* d_in, const int* in_sizes, int n_in,
                              void* d_out, int out_size)
{
    const float* users_feature   = (const float*)d_in[0];
    const float* items_feature   = (const float*)d_in[1];
    const float* bundles_feature = (const float*)d_in[2];
    const float* Wq    = (const float*)d_in[3];
    const float* Wk    = (const float*)d_in[4];
    const float* Wv    = (const float*)d_in[5];
    const float* Wo    = (const float*)d_in[6];
    const float* W_ub  = (const float*)d_in[7];
    const float* b_ub  = (const float*)d_in[8];
    // d_in[9]  W_ui   (dead)
    // d_in[10] b_ui   (dead)
    const float* att_b_w = (const float*)d_in[11];
    // d_in[12] att_i_w (dead)
    const float* p1_W  = (const float*)d_in[13];
    const float* p1_b  = (const float*)d_in[14];
    const float* p2_W  = (const float*)d_in[15];
    const float* p2_b  = (const float*)d_in[16];
    const float* A_i   = (const float*)d_in[17];
    const float* B_i   = (const float*)d_in[18];
    const float* bi_avg = (const float*)d_in[19];
    const float* ui_avg = (const float*)d_in[20];
    const float* ub_avg = (const float*)d_in[21];
    // d_in[22] ib_avg   (dead)
    const float* ub_graph = (const float*)d_in[23];
    // d_in[24] ui_graph (dead, 329MB saved)
    const int* users   = (const int*)d_in[25];
    const int* bundles = (const int*)d_in[26];

    float* base = nullptr;
    cudaGetSymbolAddress((void**)&base, g_scratch);
    float* it0   = base + OFF_IT0;
    float* q     = base + OFF_Q;
    float* k     = base + OFF_K;
    float* v     = base + OFF_V;
    float* ctx   = base + OFF_CTX;
    float* items = base + OFF_ITEMS;
    float* P     = base + OFF_P;
    float* b1    = base + OFF_B1;
    float* fub0  = base + OFF_FUB0;
    float* tbuf  = base + OFF_T;
    float* fub   = base + OFF_FUB;
    float* allub = base + OFF_ALLUB;

    // 1. items0 = relu(A_i@xf) + relu(B_i@xf) + xf
    scan_spmm_kernel<<<384, 256>>>(A_i, I_DIM, items_feature,
                                   B_i, I_DIM, items_feature,
                                   items_feature, nullptr, it0, nullptr, I_DIM);
    // 2. q,k,v (q pre-scaled by 1/sqrt(8))
    qkv_kernel<<<96, 256>>>(it0, Wq, Wk, Wv, q, k, v, I_DIM);
    // 3. attention -> ctx
    attn_kernel<<<3072, 256>>>(q, k, v, ctx);
    // 4. items = ctx @ Wo
    gemm64_kernel<<<96, 256>>>(ctx, Wo, items, I_DIM);
    // 5. P = relu(bi_avg@items); bundles_f = P + bundles_feature -> fub0[U:]
    scan_spmm_kernel<<<375, 256>>>(bi_avg, I_DIM, items,
                                   nullptr, 0, nullptr,
                                   bundles_feature, nullptr,
                                   fub0 + (size_t)U_DIM * 64, P, B_DIM);
    // 6. users_f = relu(ui_avg@items) + relu(ub_avg@bundles_f) + users_feature -> fub0[:U]
    scan_spmm_kernel<<<750, 256>>>(ui_avg, I_DIM, items,
                                   ub_avg, B_DIM, fub0 + (size_t)U_DIM * 64,
                                   users_feature, nullptr, fub0, nullptr, U_DIM);
    // 7. t = fub0 @ W_ub
    gemm64_kernel<<<282, 256>>>(fub0, W_ub, tbuf, UB_DIM);
    // 8. f_ub = relu(ub_graph @ t + b_ub)
    scan_spmm_kernel<<<1125, 256>>>(ub_graph, UB_DIM, tbuf,
                                    nullptr, 0, nullptr,
                                    nullptr, b_ub, fub, nullptr, UB_DIM);
    // 9. b1 = l2norm(P)
    l2norm_kernel<<<375, 256>>>(P, b1, B_DIM);
    // 10. att2 fusion + all_ub assembly
    att2_allub_kernel<<<1125, 256>>>(fub0, b1, fub, att_b_w, allub);
    // 11. gather + MLP -> out
    final_kernel<<<512, 256>>>(allub, users, bundles, p1_W, p1_b, p2_W, p2_b,
                               (float*)d_out, BATCH);
}

// round 2
// speedup vs baseline: 1.5899x; 1.5899x over previous
#include <cuda_runtime.h>
#include <cuda_bf16.h>
#include <math.h>

#define U_DIM 6000
#define I_DIM 3072
#define B_DIM 3000
#define EMB 64
#define HEADS 8
#define BATCH 4096
#define UB_DIM 9000   // U + B

// ---------------------------------------------------------------------------
// Scratch
// ---------------------------------------------------------------------------
__device__ float g_scratch[5019648];

#define OFF_IT0    0
#define OFF_Q      196608
#define OFF_K      393216
#define OFF_V      589824
#define OFF_CTX    786432
#define OFF_ITEMS  983040
#define OFF_P      1179648
#define OFF_B1     1371648
#define OFF_FUB0   1563648
#define OFF_T      2139648
#define OFF_FUB    2715648
#define OFF_ALLUB  3291648

// ---------------------------------------------------------------------------
// Packed f32x2 helpers (Blackwell FFMA2 path)
// ---------------------------------------------------------------------------
typedef unsigned long long u64;

__device__ __forceinline__ u64 pack2(float lo, float hi) {
    u64 r;
    asm("mov.b64 %0, {%1, %2};" : "=l"(r) : "f"(lo), "f"(hi));
    return r;
}
__device__ __forceinline__ void unpack2(u64 v, float& lo, float& hi) {
    asm("mov.b64 {%0, %1}, %2;" : "=f"(lo), "=f"(hi) : "l"(v));
}
__device__ __forceinline__ u64 fma2(u64 a, u64 b, u64 c) {
    u64 d;
    asm("fma.rn.f32x2 %0, %1, %2, %3;" : "=l"(d) : "l"(a), "l"(b), "l"(c));
    return d;
}
__device__ __forceinline__ u64 mul2(u64 a, u64 b) {
    u64 d;
    asm("mul.rn.f32x2 %0, %1, %2;" : "=l"(d) : "l"(a), "l"(b));
    return d;
}

// ---------------------------------------------------------------------------
// Warp-scan SpMM with dual-load (MLP>=2)
// ---------------------------------------------------------------------------
__device__ __forceinline__ void scan_sub(unsigned m, float v, int base4, int sub,
                                         const float* __restrict__ X, int lane,
                                         float& a0, float& a1)
{
    while (m) {
        int j = __ffs(m) - 1;
        m &= m - 1;
        float val = __shfl_sync(0xffffffffu, v, j);
        const float* xr = X + (size_t)((base4 + j) * 4 + sub) * 64;
        a0 = fmaf(val, xr[lane], a0);
        a1 = fmaf(val, xr[lane + 32], a1);
    }
}

__device__ __forceinline__ void scan_quad(float4 v, int base4,
                                          const float* __restrict__ X, int lane,
                                          float& a0, float& a1)
{
    unsigned ma = __ballot_sync(0xffffffffu, v.x != 0.f);
    unsigned mb = __ballot_sync(0xffffffffu, v.y != 0.f);
    unsigned mc = __ballot_sync(0xffffffffu, v.z != 0.f);
    unsigned md = __ballot_sync(0xffffffffu, v.w != 0.f);
    scan_sub(ma, v.x, base4, 0, X, lane, a0, a1);
    scan_sub(mb, v.y, base4, 1, X, lane, a0, a1);
    scan_sub(mc, v.z, base4, 2, X, lane, a0, a1);
    scan_sub(md, v.w, base4, 3, X, lane, a0, a1);
}

__device__ __forceinline__ void scan_row(const float* __restrict__ G, int K,
                                         const float* __restrict__ X,
                                         int row, int lane, float& a0, float& a1)
{
    const float4* g4 = reinterpret_cast<const float4*>(G + (size_t)row * K);
    int nf4 = K >> 2;
    for (int base = 0; base < nf4; base += 64) {
        int ia = base + lane, ib = base + 32 + lane;
        float4 va = make_float4(0.f, 0.f, 0.f, 0.f);
        float4 vb = make_float4(0.f, 0.f, 0.f, 0.f);
        if (ia < nf4) va = __ldg(g4 + ia);
        if (ib < nf4) vb = __ldg(g4 + ib);
        scan_quad(va, base, X, lane, a0, a1);
        scan_quad(vb, base + 32, X, lane, a0, a1);
    }
}

__global__ void scan_spmm_kernel(const float* __restrict__ G1, int K1,
                                 const float* __restrict__ X1,
                                 const float* __restrict__ G2, int K2,
                                 const float* __restrict__ X2,
                                 const float* __restrict__ addv,
                                 const float* __restrict__ bias,
                                 float* __restrict__ out,
                                 float* __restrict__ out2, int R)
{
    int row = (int)((blockIdx.x * blockDim.x + threadIdx.x) >> 5);
    if (row >= R) return;
    int lane = threadIdx.x & 31;

    float a0 = 0.f, a1 = 0.f;
    scan_row(G1, K1, X1, row, lane, a0, a1);
    float r0 = a0 + (bias ? bias[lane] : 0.f);
    float r1 = a1 + (bias ? bias[lane + 32] : 0.f);
    r0 = fmaxf(r0, 0.f);
    r1 = fmaxf(r1, 0.f);
    if (out2) {
        out2[(size_t)row * 64 + lane] = r0;
        out2[(size_t)row * 64 + lane + 32] = r1;
    }
    float o0 = r0, o1 = r1;
    if (G2) {
        float b0 = 0.f, b1v = 0.f;
        scan_row(G2, K2, X2, row, lane, b0, b1v);
        o0 += fmaxf(b0, 0.f);
        o1 += fmaxf(b1v, 0.f);
    }
    if (addv) {
        o0 += addv[(size_t)row * 64 + lane];
        o1 += addv[(size_t)row * 64 + lane + 32];
    }
    out[(size_t)row * 64 + lane] = o0;
    out[(size_t)row * 64 + lane + 32] = o1;
}

// ---------------------------------------------------------------------------
// QKV projection: X tile staged in smem; thread handles 8 rows x 1 col x 3 mats
// ---------------------------------------------------------------------------
__global__ void qkv_kernel(const float* __restrict__ X,
                           const float* __restrict__ Wq,
                           const float* __restrict__ Wk,
                           const float* __restrict__ Wv,
                           float* __restrict__ q, float* __restrict__ k,
                           float* __restrict__ v, int N)
{
    __shared__ float wq[4096], wk[4096], wv[4096], xs[2048];
    int t = threadIdx.x;
    for (int i = t; i < 1024; i += 256) {
        ((float4*)wq)[i] = ((const float4*)Wq)[i];
        ((float4*)wk)[i] = ((const float4*)Wk)[i];
        ((float4*)wv)[i] = ((const float4*)Wv)[i];
    }
    int row0 = blockIdx.x * 32;
    for (int i = t; i < 512; i += 256) {
        int r = row0 + (i >> 4);
        if (r < N)
            ((float4*)xs)[i] = ((const float4*)X)[(size_t)r * 16 + (i & 15)];
    }
    __syncthreads();
    int col = t & 63, rl = t >> 6;
    float aq[8], ak[8], av[8];
#pragma unroll
    for (int r = 0; r < 8; r++) { aq[r] = 0.f; ak[r] = 0.f; av[r] = 0.f; }
    for (int kk = 0; kk < 64; kk++) {
        float wqv = wq[kk * 64 + col];
        float wkv = wk[kk * 64 + col];
        float wvv = wv[kk * 64 + col];
#pragma unroll
        for (int r = 0; r < 8; r++) {
            float xv = xs[(rl + r * 4) * 64 + kk];
            aq[r] = fmaf(xv, wqv, aq[r]);
            ak[r] = fmaf(xv, wkv, ak[r]);
            av[r] = fmaf(xv, wvv, av[r]);
        }
    }
#pragma unroll
    for (int r = 0; r < 8; r++) {
        int rr = row0 + rl + r * 4;
        if (rr < N) {
            q[(size_t)rr * 64 + col] = aq[r] * 0.3535533905932738f;
            k[(size_t)rr * 64 + col] = ak[r];
            v[(size_t)rr * 64 + col] = av[r];
        }
    }
}

// ---------------------------------------------------------------------------
// Small GEMM: out = X (N x 64) @ W (64 x 64), X tile in smem
// ---------------------------------------------------------------------------
__global__ void gemm64_kernel(const float* __restrict__ X,
                              const float* __restrict__ W,
                              float* __restrict__ out, int N)
{
    __shared__ float ws[4096], xs[2048];
    int t = threadIdx.x;
    for (int i = t; i < 1024; i += 256)
        ((float4*)ws)[i] = ((const float4*)W)[i];
    int row0 = blockIdx.x * 32;
    for (int i = t; i < 512; i += 256) {
        int r = row0 + (i >> 4);
        if (r < N)
            ((float4*)xs)[i] = ((const float4*)X)[(size_t)r * 16 + (i & 15)];
    }
    __syncthreads();
    int col = t & 63, rl = t >> 6;
    float acc[8];
#pragma unroll
    for (int r = 0; r < 8; r++) acc[r] = 0.f;
    for (int kk = 0; kk < 64; kk++) {
        float w = ws[kk * 64 + col];
#pragma unroll
        for (int r = 0; r < 8; r++)
            acc[r] = fmaf(xs[(rl + r * 4) * 64 + kk], w, acc[r]);
    }
#pragma unroll
    for (int r = 0; r < 8; r++) {
        int rr = row0 + rl + r * 4;
        if (rr < N) out[(size_t)rr * 64 + col] = acc[r];
    }
}

// ---------------------------------------------------------------------------
// Flash attention: 8 heads, dh=8, N=3072.
// 4 rows per warp (amortize K/V smem reads), f32x2 FFMA2 math.
// Block = 8 warps = 32 rows. Grid = 8 heads * 96 = 768 blocks.
// ---------------------------------------------------------------------------
#define AT_CHUNK 512
__global__ __launch_bounds__(256) void attn_kernel(const float* __restrict__ qg,
                                                   const float* __restrict__ kg,
                                                   const float* __restrict__ vg,
                                                   float* __restrict__ ctx)
{
    __shared__ float4 ks4[AT_CHUNK * 2];
    __shared__ float4 vs4[AT_CHUNK * 2];
    int t = threadIdx.x;
    int warp = t >> 5, lane = t & 31;
    int head = blockIdx.x / 96;
    int rowbase = (blockIdx.x % 96) * 32 + warp * 4;
    int h8 = head * 8;

    u64 q2[4][4];
#pragma unroll
    for (int r = 0; r < 4; r++) {
        const float4* qp = reinterpret_cast<const float4*>(
            qg + (size_t)(rowbase + r) * 64 + h8);
        float4 a = qp[0], b = qp[1];
        q2[r][0] = pack2(a.x, a.y); q2[r][1] = pack2(a.z, a.w);
        q2[r][2] = pack2(b.x, b.y); q2[r][3] = pack2(b.z, b.w);
    }

    float mx[4], sm[4];
    u64 acc2[4][4];
#pragma unroll
    for (int r = 0; r < 4; r++) {
        mx[r] = -1e30f; sm[r] = 0.f;
#pragma unroll
        for (int j = 0; j < 4; j++) acc2[r][j] = 0ull;
    }

    for (int m0 = 0; m0 < I_DIM; m0 += AT_CHUNK) {
        for (int idx = t; idx < AT_CHUNK * 2; idx += 256) {
            int i = idx >> 1, part = idx & 1;
            ks4[idx] = *reinterpret_cast<const float4*>(
                kg + (size_t)(m0 + i) * 64 + h8 + part * 4);
            vs4[idx] = *reinterpret_cast<const float4*>(
                vg + (size_t)(m0 + i) * 64 + h8 + part * 4);
        }
        __syncthreads();
        for (int mm = lane; mm < AT_CHUNK; mm += 32) {
            float4 ka = ks4[mm * 2], kb = ks4[mm * 2 + 1];
            u64 k2[4];
            k2[0] = pack2(ka.x, ka.y); k2[1] = pack2(ka.z, ka.w);
            k2[2] = pack2(kb.x, kb.y); k2[3] = pack2(kb.z, kb.w);
            float4 va = vs4[mm * 2], vb = vs4[mm * 2 + 1];
            u64 v2[4];
            v2[0] = pack2(va.x, va.y); v2[1] = pack2(va.z, va.w);
            v2[2] = pack2(vb.x, vb.y); v2[3] = pack2(vb.z, vb.w);
#pragma unroll
            for (int r = 0; r < 4; r++) {
                u64 s2 = 0ull;
                s2 = fma2(q2[r][0], k2[0], s2);
                s2 = fma2(q2[r][1], k2[1], s2);
                s2 = fma2(q2[r][2], k2[2], s2);
                s2 = fma2(q2[r][3], k2[3], s2);
                float slo, shi; unpack2(s2, slo, shi);
                float s = slo + shi;
                float p;
                if (s > mx[r]) {
                    float c = __expf(mx[r] - s);
                    sm[r] *= c;
                    u64 c2 = pack2(c, c);
#pragma unroll
                    for (int j = 0; j < 4; j++)
                        acc2[r][j] = mul2(acc2[r][j], c2);
                    mx[r] = s;
                    p = 1.f;
                } else {
                    p = __expf(s - mx[r]);
                }
                sm[r] += p;
                u64 p2 = pack2(p, p);
#pragma unroll
                for (int j = 0; j < 4; j++)
                    acc2[r][j] = fma2(p2, v2[j], acc2[r][j]);
            }
        }
        __syncthreads();
    }

    // merge lane partials per row
#pragma unroll
    for (int r = 0; r < 4; r++) {
        float M = mx[r];
#pragma unroll
        for (int o = 16; o; o >>= 1)
            M = fmaxf(M, __shfl_xor_sync(0xffffffffu, M, o));
        float c = __expf(mx[r] - M);
        float s = sm[r] * c;
        float a[8];
#pragma unroll
        for (int j = 0; j < 4; j++) {
            float lo, hi; unpack2(acc2[r][j], lo, hi);
            a[2 * j] = lo * c; a[2 * j + 1] = hi * c;
        }
#pragma unroll
        for (int o = 16; o; o >>= 1) {
            s += __shfl_xor_sync(0xffffffffu, s, o);
#pragma unroll
            for (int d = 0; d < 8; d++)
                a[d] += __shfl_xor_sync(0xffffffffu, a[d], o);
        }
        if (lane == 0) {
            float inv = 1.f / s;
            float* op = ctx + (size_t)(rowbase + r) * 64 + h8;
#pragma unroll
            for (int d = 0; d < 8; d++) op[d] = a[d] * inv;
        }
    }
}

// ---------------------------------------------------------------------------
// Row-wise L2 normalize
// ---------------------------------------------------------------------------
__global__ void l2norm_kernel(const float* __restrict__ X, float* __restrict__ out, int R)
{
    int row = (int)((blockIdx.x * blockDim.x + threadIdx.x) >> 5);
    if (row >= R) return;
    int lane = threadIdx.x & 31;
    float v0 = X[(size_t)row * 64 + lane];
    float v1 = X[(size_t)row * 64 + lane + 32];
    float ss = v0 * v0 + v1 * v1;
#pragma unroll
    for (int o = 16; o; o >>= 1) ss += __shfl_xor_sync(0xffffffffu, ss, o);
    float inv = 1.f / fmaxf(sqrtf(ss), 1e-12f);
    out[(size_t)row * 64 + lane] = v0 * inv;
    out[(size_t)row * 64 + lane + 32] = v1 * inv;
}

// ---------------------------------------------------------------------------
// _att2 fusion + all_ub assembly
// ---------------------------------------------------------------------------
__global__ void att2_allub_kernel(const float* __restrict__ f_ub0,
                                  const float* __restrict__ b1,
                                  const float* __restrict__ f_ub,
                                  const float* __restrict__ attw,
                                  float* __restrict__ all_ub)
{
    int row = (int)((blockIdx.x * blockDim.x + threadIdx.x) >> 5);
    if (row >= UB_DIM) return;
    int lane = threadIdx.x & 31;

    float x00 = f_ub0[(size_t)row * 64 + lane];
    float x01 = f_ub0[(size_t)row * 64 + lane + 32];
    float x10, x11;
    if (row < U_DIM) { x10 = x00; x11 = x01; }
    else {
        x10 = b1[(size_t)(row - U_DIM) * 64 + lane];
        x11 = b1[(size_t)(row - U_DIM) * 64 + lane + 32];
    }
    float w0 = attw[lane], w1 = attw[lane + 32];
    float l0 = x00 * w0 + x01 * w1;
    float l1 = x10 * w0 + x11 * w1;
#pragma unroll
    for (int o = 16; o; o >>= 1) {
        l0 += __shfl_xor_sync(0xffffffffu, l0, o);
        l1 += __shfl_xor_sync(0xffffffffu, l1, o);
    }
    float m = fmaxf(l0, l1);
    float e0 = __expf(l0 - m), e1 = __expf(l1 - m);
    float inv = 1.f / (e0 + e1);
    float a0 = e0 * inv, a1 = e1 * inv;
    float fu0 = a0 * x00 + a1 * x10;
    float fu1 = a0 * x01 + a1 * x11;

    float g0 = f_ub[(size_t)row * 64 + lane];
    float g1 = f_ub[(size_t)row * 64 + lane + 32];
    float ss = g0 * g0 + g1 * g1 + fu0 * fu0 + fu1 * fu1;
#pragma unroll
    for (int o = 16; o; o >>= 1) ss += __shfl_xor_sync(0xffffffffu, ss, o);
    float invn = 1.f / fmaxf(sqrtf(ss), 1e-12f);

    size_t ob = (size_t)row * 192;
    all_ub[ob + lane] = x00;
    all_ub[ob + 32 + lane] = x01;
    all_ub[ob + 64 + lane] = g0 * invn;
    all_ub[ob + 96 + lane] = g1 * invn;
    all_ub[ob + 128 + lane] = fu0 * invn;
    all_ub[ob + 160 + lane] = fu1 * invn;
}

// ---------------------------------------------------------------------------
// Final gather + MLP
// ---------------------------------------------------------------------------
__global__ void final_kernel(const float* __restrict__ all_ub,
                             const int* __restrict__ users,
                             const int* __restrict__ bundles,
                             const float* __restrict__ p1W,
                             const float* __restrict__ p1b,
                             const float* __restrict__ p2W,
                             const float* __restrict__ p2b,
                             float* __restrict__ out, int batch)
{
    int b = (int)((blockIdx.x * blockDim.x + threadIdx.x) >> 5);
    if (b >= batch) return;
    int lane = threadIdx.x & 31;
    const float* ue = all_ub + (size_t)users[b] * 192;
    const float* be = all_ub + (size_t)(U_DIM + bundles[b]) * 192;

    float acc[8];
#pragma unroll
    for (int j = 0; j < 8; j++) acc[j] = 0.f;

    for (int i = 0; i < 18; i++) {
        int e0 = lane + 32 * i;
        float val;
        if (e0 < 192) val = ue[e0] * be[e0];
        else if (e0 < 384) val = be[e0 - 192];
        else val = ue[e0 - 384];
        const float4* wr = reinterpret_cast<const float4*>(p1W + (size_t)e0 * 8);
        float4 wa = wr[0], wb = wr[1];
        acc[0] = fmaf(val, wa.x, acc[0]); acc[1] = fmaf(val, wa.y, acc[1]);
        acc[2] = fmaf(val, wa.z, acc[2]); acc[3] = fmaf(val, wa.w, acc[3]);
        acc[4] = fmaf(val, wb.x, acc[4]); acc[5] = fmaf(val, wb.y, acc[5]);
        acc[6] = fmaf(val, wb.z, acc[6]); acc[7] = fmaf(val, wb.w, acc[7]);
    }
#pragma unroll
    for (int o = 16; o; o >>= 1) {
#pragma unroll
        for (int j = 0; j < 8; j++)
            acc[j] += __shfl_xor_sync(0xffffffffu, acc[j], o);
    }
    if (lane == 0) {
        float r = p2b[0];
#pragma unroll
        for (int j = 0; j < 8; j++)
            r += fmaxf(acc[j] + p1b[j], 0.f) * p2W[j];
        out[b] = r;
    }
}

// ---------------------------------------------------------------------------
// Launcher
// ---------------------------------------------------------------------------
extern "C" void kernel_launch(void* const* d_in, const int* in_sizes, int n_in,
                              void* d_out, int out_size)
{
    const float* users_feature   = (const float*)d_in[0];
    const float* items_feature   = (const float*)d_in[1];
    const float* bundles_feature = (const float*)d_in[2];
    const float* Wq    = (const float*)d_in[3];
    const float* Wk    = (const float*)d_in[4];
    const float* Wv    = (const float*)d_in[5];
    const float* Wo    = (const float*)d_in[6];
    const float* W_ub  = (const float*)d_in[7];
    const float* b_ub  = (const float*)d_in[8];
    const float* att_b_w = (const float*)d_in[11];
    const float* p1_W  = (const float*)d_in[13];
    const float* p1_b  = (const float*)d_in[14];
    const float* p2_W  = (const float*)d_in[15];
    const float* p2_b  = (const float*)d_in[16];
    const float* A_i   = (const float*)d_in[17];
    const float* B_i   = (const float*)d_in[18];
    const float* bi_avg = (const float*)d_in[19];
    const float* ui_avg = (const float*)d_in[20];
    const float* ub_avg = (const float*)d_in[21];
    const float* ub_graph = (const float*)d_in[23];
    const int* users   = (const int*)d_in[25];
    const int* bundles = (const int*)d_in[26];

    float* base = nullptr;
    cudaGetSymbolAddress((void**)&base, g_scratch);
    float* it0   = base + OFF_IT0;
    float* q     = base + OFF_Q;
    float* k     = base + OFF_K;
    float* v     = base + OFF_V;
    float* ctx   = base + OFF_CTX;
    float* items = base + OFF_ITEMS;
    float* P     = base + OFF_P;
    float* b1    = base + OFF_B1;
    float* fub0  = base + OFF_FUB0;
    float* tbuf  = base + OFF_T;
    float* fub   = base + OFF_FUB;
    float* allub = base + OFF_ALLUB;

    // 1. items0 = relu(A_i@xf) + relu(B_i@xf) + xf
    scan_spmm_kernel<<<384, 256>>>(A_i, I_DIM, items_feature,
                                   B_i, I_DIM, items_feature,
                                   items_feature, nullptr, it0, nullptr, I_DIM);
    // 2. q,k,v (q pre-scaled)
    qkv_kernel<<<96, 256>>>(it0, Wq, Wk, Wv, q, k, v, I_DIM);
    // 3. attention -> ctx
    attn_kernel<<<768, 256>>>(q, k, v, ctx);
    // 4. items = ctx @ Wo
    gemm64_kernel<<<96, 256>>>(ctx, Wo, items, I_DIM);
    // 5. P = relu(bi_avg@items); bundles_f = P + bundles_feature
    scan_spmm_kernel<<<375, 256>>>(bi_avg, I_DIM, items,
                                   nullptr, 0, nullptr,
                                   bundles_feature, nullptr,
                                   fub0 + (size_t)U_DIM * 64, P, B_DIM);
    // 6. users_f
    scan_spmm_kernel<<<750, 256>>>(ui_avg, I_DIM, items,
                                   ub_avg, B_DIM, fub0 + (size_t)U_DIM * 64,
                                   users_feature, nullptr, fub0, nullptr, U_DIM);
    // 7. t = fub0 @ W_ub
    gemm64_kernel<<<282, 256>>>(fub0, W_ub, tbuf, UB_DIM);
    // 8. f_ub = relu(ub_graph @ t + b_ub)
    scan_spmm_kernel<<<1125, 256>>>(ub_graph, UB_DIM, tbuf,
                                    nullptr, 0, nullptr,
                                    nullptr, b_ub, fub, nullptr, UB_DIM);
    // 9. b1 = l2norm(P)
    l2norm_kernel<<<375, 256>>>(P, b1, B_DIM);
    // 10. att2 fusion + all_ub assembly
    att2_allub_kernel<<<1125, 256>>>(fub0, b1, fub, att_b_w, allub);
    // 11. gather + MLP -> out
    final_kernel<<<512, 256>>>(allub, users, bundles, p1_W, p1_b, p2_W, p2_b,
                               (float*)d_out, BATCH);
}

// round 3
// speedup vs baseline: 1.6655x; 1.0476x over previous
#include <cuda_runtime.h>
#include <cuda_bf16.h>
#include <math.h>

#define U_DIM 6000
#define I_DIM 3072
#define B_DIM 3000
#define EMB 64
#define HEADS 8
#define BATCH 4096
#define UB_DIM 9000   // U + B

// ---------------------------------------------------------------------------
// Scratch
// ---------------------------------------------------------------------------
__device__ float g_scratch[5019648];
__device__ int g_needed[UB_DIM];

#define OFF_IT0    0
#define OFF_Q      196608
#define OFF_K      393216
#define OFF_V      589824
#define OFF_CTX    786432
#define OFF_ITEMS  983040
#define OFF_P      1179648
#define OFF_FUB0   1563648
#define OFF_T      2139648
#define OFF_FUB    2715648
#define OFF_ALLUB  3291648

// ---------------------------------------------------------------------------
// Packed f32x2 helpers (Blackwell FFMA2 path)
// ---------------------------------------------------------------------------
typedef unsigned long long u64;

__device__ __forceinline__ u64 pack2(float lo, float hi) {
    u64 r;
    asm("mov.b64 %0, {%1, %2};" : "=l"(r) : "f"(lo), "f"(hi));
    return r;
}
__device__ __forceinline__ void unpack2(u64 v, float& lo, float& hi) {
    asm("mov.b64 {%0, %1}, %2;" : "=f"(lo), "=f"(hi) : "l"(v));
}
__device__ __forceinline__ u64 fma2(u64 a, u64 b, u64 c) {
    u64 d;
    asm("fma.rn.f32x2 %0, %1, %2, %3;" : "=l"(d) : "l"(a), "l"(b), "l"(c));
    return d;
}
__device__ __forceinline__ u64 mul2(u64 a, u64 b) {
    u64 d;
    asm("mul.rn.f32x2 %0, %1, %2;" : "=l"(d) : "l"(a), "l"(b));
    return d;
}

// ---------------------------------------------------------------------------
// Warp-scan SpMM, software-pipelined: 4 float4/lane per block, prefetch next
// block before scanning current -> MLP stays >= 4 through the whole row.
// ---------------------------------------------------------------------------
__device__ __forceinline__ void scan_sub(unsigned m, float v, int base4, int sub,
                                         const float* __restrict__ X, int lane,
                                         float& a0, float& a1)
{
    while (m) {
        int j = __ffs(m) - 1;
        m &= m - 1;
        float val = __shfl_sync(0xffffffffu, v, j);
        const float* xr = X + (size_t)((base4 + j) * 4 + sub) * 64;
        a0 = fmaf(val, xr[lane], a0);
        a1 = fmaf(val, xr[lane + 32], a1);
    }
}

__device__ __forceinline__ void scan_quad(float4 v, int base4,
                                          const float* __restrict__ X, int lane,
                                          float& a0, float& a1)
{
    unsigned ma = __ballot_sync(0xffffffffu, v.x != 0.f);
    unsigned mb = __ballot_sync(0xffffffffu, v.y != 0.f);
    unsigned mc = __ballot_sync(0xffffffffu, v.z != 0.f);
    unsigned md = __ballot_sync(0xffffffffu, v.w != 0.f);
    scan_sub(ma, v.x, base4, 0, X, lane, a0, a1);
    scan_sub(mb, v.y, base4, 1, X, lane, a0, a1);
    scan_sub(mc, v.z, base4, 2, X, lane, a0, a1);
    scan_sub(md, v.w, base4, 3, X, lane, a0, a1);
}

__device__ __forceinline__ void scan_row(const float* __restrict__ G, int K,
                                         const float* __restrict__ X,
                                         int row, int lane, float& a0, float& a1)
{
    const float4* g4 = reinterpret_cast<const float4*>(G + (size_t)row * K);
    int nf4 = K >> 2;
    float4 cur[4];
#pragma unroll
    for (int j = 0; j < 4; j++) {
        int idx = lane + 32 * j;
        cur[j] = (idx < nf4) ? __ldg(g4 + idx) : make_float4(0.f, 0.f, 0.f, 0.f);
    }
    for (int base = 0; base < nf4; base += 128) {
        float4 nxt[4];
        int nb = base + 128;
#pragma unroll
        for (int j = 0; j < 4; j++) {
            int idx = nb + lane + 32 * j;
            nxt[j] = (idx < nf4) ? __ldg(g4 + idx) : make_float4(0.f, 0.f, 0.f, 0.f);
        }
#pragma unroll
        for (int j = 0; j < 4; j++)
            scan_quad(cur[j], base + 32 * j, X, lane, a0, a1);
#pragma unroll
        for (int j = 0; j < 4; j++) cur[j] = nxt[j];
    }
}

__global__ void scan_spmm_kernel(const float* __restrict__ G1, int K1,
                                 const float* __restrict__ X1,
                                 const float* __restrict__ G2, int K2,
                                 const float* __restrict__ X2,
                                 const float* __restrict__ addv,
                                 const float* __restrict__ bias,
                                 const int* __restrict__ needed,
                                 float* __restrict__ out,
                                 float* __restrict__ out2, int R)
{
    int row = (int)((blockIdx.x * blockDim.x + threadIdx.x) >> 5);
    if (row >= R) return;
    if (needed && !needed[row]) return;
    int lane = threadIdx.x & 31;

    float a0 = 0.f, a1 = 0.f;
    scan_row(G1, K1, X1, row, lane, a0, a1);
    float r0 = a0 + (bias ? bias[lane] : 0.f);
    float r1 = a1 + (bias ? bias[lane + 32] : 0.f);
    r0 = fmaxf(r0, 0.f);
    r1 = fmaxf(r1, 0.f);
    if (out2) {
        out2[(size_t)row * 64 + lane] = r0;
        out2[(size_t)row * 64 + lane + 32] = r1;
    }
    float o0 = r0, o1 = r1;
    if (G2) {
        float b0 = 0.f, b1v = 0.f;
        scan_row(G2, K2, X2, row, lane, b0, b1v);
        o0 += fmaxf(b0, 0.f);
        o1 += fmaxf(b1v, 0.f);
    }
    if (addv) {
        o0 += addv[(size_t)row * 64 + lane];
        o1 += addv[(size_t)row * 64 + lane + 32];
    }
    out[(size_t)row * 64 + lane] = o0;
    out[(size_t)row * 64 + lane + 32] = o1;
}

// ---------------------------------------------------------------------------
// needed-row flags
// ---------------------------------------------------------------------------
__global__ void flags_zero_kernel() {
    int i = blockIdx.x * 256 + threadIdx.x;
    if (i < UB_DIM) g_needed[i] = 0;
}
__global__ void flags_set_kernel(const int* __restrict__ users,
                                 const int* __restrict__ bundles) {
    int i = blockIdx.x * 256 + threadIdx.x;
    if (i < BATCH) {
        g_needed[users[i]] = 1;
        g_needed[U_DIM + bundles[i]] = 1;
    }
}

// ---------------------------------------------------------------------------
// QKV projection: 16-row tiles, 4 rows/thread, float4 X reads
// ---------------------------------------------------------------------------
__global__ __launch_bounds__(256) void qkv_kernel(const float* __restrict__ X,
                           const float* __restrict__ Wq,
                           const float* __restrict__ Wk,
                           const float* __restrict__ Wv,
                           float* __restrict__ q, float* __restrict__ k,
                           float* __restrict__ v, int N)
{
    __shared__ float wq[4096], wk[4096], wv[4096], xs[1024];
    int t = threadIdx.x;
    for (int i = t; i < 1024; i += 256) {
        ((float4*)wq)[i] = ((const float4*)Wq)[i];
        ((float4*)wk)[i] = ((const float4*)Wk)[i];
        ((float4*)wv)[i] = ((const float4*)Wv)[i];
    }
    int row0 = blockIdx.x * 16;
    if (t < 256) {
        int r = row0 + (t >> 4);
        ((float4*)xs)[t] = (r < N) ? ((const float4*)X)[(size_t)r * 16 + (t & 15)]
                                   : make_float4(0.f, 0.f, 0.f, 0.f);
    }
    __syncthreads();
    int col = t & 63, rl = t >> 6;
    float aq[4] = {0, 0, 0, 0}, ak[4] = {0, 0, 0, 0}, av[4] = {0, 0, 0, 0};
    for (int k4 = 0; k4 < 16; k4++) {
        float4 xv[4];
#pragma unroll
        for (int r = 0; r < 4; r++)
            xv[r] = ((float4*)xs)[(rl + r * 4) * 16 + k4];
#pragma unroll
        for (int s = 0; s < 4; s++) {
            int kk = k4 * 4 + s;
            float wqv = wq[kk * 64 + col];
            float wkv = wk[kk * 64 + col];
            float wvv = wv[kk * 64 + col];
#pragma unroll
            for (int r = 0; r < 4; r++) {
                float x = (s == 0) ? xv[r].x : (s == 1) ? xv[r].y
                          : (s == 2) ? xv[r].z : xv[r].w;
                aq[r] = fmaf(x, wqv, aq[r]);
                ak[r] = fmaf(x, wkv, ak[r]);
                av[r] = fmaf(x, wvv, av[r]);
            }
        }
    }
#pragma unroll
    for (int r = 0; r < 4; r++) {
        int rr = row0 + rl + r * 4;
        if (rr < N) {
            q[(size_t)rr * 64 + col] = aq[r] * 0.3535533905932738f;
            k[(size_t)rr * 64 + col] = ak[r];
            v[(size_t)rr * 64 + col] = av[r];
        }
    }
}

// ---------------------------------------------------------------------------
// Small GEMM: out = X (N x 64) @ W (64 x 64); 16-row tiles
// ---------------------------------------------------------------------------
__global__ __launch_bounds__(256) void gemm64_kernel(const float* __restrict__ X,
                              const float* __restrict__ W,
                              float* __restrict__ out, int N)
{
    __shared__ float ws[4096], xs[1024];
    int t = threadIdx.x;
    for (int i = t; i < 1024; i += 256)
        ((float4*)ws)[i] = ((const float4*)W)[i];
    int row0 = blockIdx.x * 16;
    if (t < 256) {
        int r = row0 + (t >> 4);
        ((float4*)xs)[t] = (r < N) ? ((const float4*)X)[(size_t)r * 16 + (t & 15)]
                                   : make_float4(0.f, 0.f, 0.f, 0.f);
    }
    __syncthreads();
    int col = t & 63, rl = t >> 6;
    float acc[4] = {0, 0, 0, 0};
    for (int k4 = 0; k4 < 16; k4++) {
        float4 xv[4];
#pragma unroll
        for (int r = 0; r < 4; r++)
            xv[r] = ((float4*)xs)[(rl + r * 4) * 16 + k4];
#pragma unroll
        for (int s = 0; s < 4; s++) {
            float w = ws[(k4 * 4 + s) * 64 + col];
#pragma unroll
            for (int r = 0; r < 4; r++) {
                float x = (s == 0) ? xv[r].x : (s == 1) ? xv[r].y
                          : (s == 2) ? xv[r].z : xv[r].w;
                acc[r] = fmaf(x, w, acc[r]);
            }
        }
    }
#pragma unroll
    for (int r = 0; r < 4; r++) {
        int rr = row0 + rl + r * 4;
        if (rr < N) out[(size_t)rr * 64 + col] = acc[r];
    }
}

// ---------------------------------------------------------------------------
// Flash attention: 8 heads, dh=8, N=3072. 4 rows/warp, f32x2 FFMA2.
// ---------------------------------------------------------------------------
#define AT_CHUNK 512
__global__ __launch_bounds__(256) void attn_kernel(const float* __restrict__ qg,
                                                   const float* __restrict__ kg,
                                                   const float* __restrict__ vg,
                                                   float* __restrict__ ctx)
{
    __shared__ float4 ks4[AT_CHUNK * 2];
    __shared__ float4 vs4[AT_CHUNK * 2];
    int t = threadIdx.x;
    int warp = t >> 5, lane = t & 31;
    int head = blockIdx.x / 96;
    int rowbase = (blockIdx.x % 96) * 32 + warp * 4;
    int h8 = head * 8;

    u64 q2[4][4];
#pragma unroll
    for (int r = 0; r < 4; r++) {
        const float4* qp = reinterpret_cast<const float4*>(
            qg + (size_t)(rowbase + r) * 64 + h8);
        float4 a = qp[0], b = qp[1];
        q2[r][0] = pack2(a.x, a.y); q2[r][1] = pack2(a.z, a.w);
        q2[r][2] = pack2(b.x, b.y); q2[r][3] = pack2(b.z, b.w);
    }

    float mx[4], sm[4];
    u64 acc2[4][4];
#pragma unroll
    for (int r = 0; r < 4; r++) {
        mx[r] = -1e30f; sm[r] = 0.f;
#pragma unroll
        for (int j = 0; j < 4; j++) acc2[r][j] = 0ull;
    }

    for (int m0 = 0; m0 < I_DIM; m0 += AT_CHUNK) {
        for (int idx = t; idx < AT_CHUNK * 2; idx += 256) {
            int i = idx >> 1, part = idx & 1;
            ks4[idx] = *reinterpret_cast<const float4*>(
                kg + (size_t)(m0 + i) * 64 + h8 + part * 4);
            vs4[idx] = *reinterpret_cast<const float4*>(
                vg + (size_t)(m0 + i) * 64 + h8 + part * 4);
        }
        __syncthreads();
        for (int mm = lane; mm < AT_CHUNK; mm += 32) {
            float4 ka = ks4[mm * 2], kb = ks4[mm * 2 + 1];
            u64 k2[4];
            k2[0] = pack2(ka.x, ka.y); k2[1] = pack2(ka.z, ka.w);
            k2[2] = pack2(kb.x, kb.y); k2[3] = pack2(kb.z, kb.w);
            float4 va = vs4[mm * 2], vb = vs4[mm * 2 + 1];
            u64 v2[4];
            v2[0] = pack2(va.x, va.y); v2[1] = pack2(va.z, va.w);
            v2[2] = pack2(vb.x, vb.y); v2[3] = pack2(vb.z, vb.w);
#pragma unroll
            for (int r = 0; r < 4; r++) {
                u64 s2 = 0ull;
                s2 = fma2(q2[r][0], k2[0], s2);
                s2 = fma2(q2[r][1], k2[1], s2);
                s2 = fma2(q2[r][2], k2[2], s2);
                s2 = fma2(q2[r][3], k2[3], s2);
                float slo, shi; unpack2(s2, slo, shi);
                float s = slo + shi;
                float p;
                if (s > mx[r]) {
                    float c = __expf(mx[r] - s);
                    sm[r] *= c;
                    u64 c2 = pack2(c, c);
#pragma unroll
                    for (int j = 0; j < 4; j++)
                        acc2[r][j] = mul2(acc2[r][j], c2);
                    mx[r] = s;
                    p = 1.f;
                } else {
                    p = __expf(s - mx[r]);
                }
                sm[r] += p;
                u64 p2 = pack2(p, p);
#pragma unroll
                for (int j = 0; j < 4; j++)
                    acc2[r][j] = fma2(p2, v2[j], acc2[r][j]);
            }
        }
        __syncthreads();
    }

#pragma unroll
    for (int r = 0; r < 4; r++) {
        float M = mx[r];
#pragma unroll
        for (int o = 16; o; o >>= 1)
            M = fmaxf(M, __shfl_xor_sync(0xffffffffu, M, o));
        float c = __expf(mx[r] - M);
        float s = sm[r] * c;
        float a[8];
#pragma unroll
        for (int j = 0; j < 4; j++) {
            float lo, hi; unpack2(acc2[r][j], lo, hi);
            a[2 * j] = lo * c; a[2 * j + 1] = hi * c;
        }
#pragma unroll
        for (int o = 16; o; o >>= 1) {
            s += __shfl_xor_sync(0xffffffffu, s, o);
#pragma unroll
            for (int d = 0; d < 8; d++)
                a[d] += __shfl_xor_sync(0xffffffffu, a[d], o);
        }
        if (lane == 0) {
            float inv = 1.f / s;
            float* op = ctx + (size_t)(rowbase + r) * 64 + h8;
#pragma unroll
            for (int d = 0; d < 8; d++) op[d] = a[d] * inv;
        }
    }
}

// ---------------------------------------------------------------------------
// _att2 fusion + inline l2norm(P) + all_ub assembly (needed rows only)
// ---------------------------------------------------------------------------
__global__ void att2_allub_kernel(const float* __restrict__ f_ub0,
                                  const float* __restrict__ P,
                                  const float* __restrict__ f_ub,
                                  const float* __restrict__ attw,
                                  float* __restrict__ all_ub)
{
    int row = (int)((blockIdx.x * blockDim.x + threadIdx.x) >> 5);
    if (row >= UB_DIM) return;
    if (!g_needed[row]) return;
    int lane = threadIdx.x & 31;

    float x00 = f_ub0[(size_t)row * 64 + lane];
    float x01 = f_ub0[(size_t)row * 64 + lane + 32];
    float x10, x11;
    if (row < U_DIM) { x10 = x00; x11 = x01; }
    else {
        float p0 = P[(size_t)(row - U_DIM) * 64 + lane];
        float p1 = P[(size_t)(row - U_DIM) * 64 + lane + 32];
        float ss = p0 * p0 + p1 * p1;
#pragma unroll
        for (int o = 16; o; o >>= 1) ss += __shfl_xor_sync(0xffffffffu, ss, o);
        float inv = 1.f / fmaxf(sqrtf(ss), 1e-12f);
        x10 = p0 * inv; x11 = p1 * inv;
    }
    float w0 = attw[lane], w1 = attw[lane + 32];
    float l0 = x00 * w0 + x01 * w1;
    float l1 = x10 * w0 + x11 * w1;
#pragma unroll
    for (int o = 16; o; o >>= 1) {
        l0 += __shfl_xor_sync(0xffffffffu, l0, o);
        l1 += __shfl_xor_sync(0xffffffffu, l1, o);
    }
    float m = fmaxf(l0, l1);
    float e0 = __expf(l0 - m), e1 = __expf(l1 - m);
    float inv = 1.f / (e0 + e1);
    float a0 = e0 * inv, a1 = e1 * inv;
    float fu0 = a0 * x00 + a1 * x10;
    float fu1 = a0 * x01 + a1 * x11;

    float g0 = f_ub[(size_t)row * 64 + lane];
    float g1 = f_ub[(size_t)row * 64 + lane + 32];
    float ss = g0 * g0 + g1 * g1 + fu0 * fu0 + fu1 * fu1;
#pragma unroll
    for (int o = 16; o; o >>= 1) ss += __shfl_xor_sync(0xffffffffu, ss, o);
    float invn = 1.f / fmaxf(sqrtf(ss), 1e-12f);

    size_t ob = (size_t)row * 192;
    all_ub[ob + lane] = x00;
    all_ub[ob + 32 + lane] = x01;
    all_ub[ob + 64 + lane] = g0 * invn;
    all_ub[ob + 96 + lane] = g1 * invn;
    all_ub[ob + 128 + lane] = fu0 * invn;
    all_ub[ob + 160 + lane] = fu1 * invn;
}

// ---------------------------------------------------------------------------
// Final gather + MLP
// ---------------------------------------------------------------------------
__global__ void final_kernel(const float* __restrict__ all_ub,
                             const int* __restrict__ users,
                             const int* __restrict__ bundles,
                             const float* __restrict__ p1W,
                             const float* __restrict__ p1b,
                             const float* __restrict__ p2W,
                             const float* __restrict__ p2b,
                             float* __restrict__ out, int batch)
{
    int b = (int)((blockIdx.x * blockDim.x + threadIdx.x) >> 5);
    if (b >= batch) return;
    int lane = threadIdx.x & 31;
    const float* ue = all_ub + (size_t)users[b] * 192;
    const float* be = all_ub + (size_t)(U_DIM + bundles[b]) * 192;

    float acc[8];
#pragma unroll
    for (int j = 0; j < 8; j++) acc[j] = 0.f;

    for (int i = 0; i < 18; i++) {
        int e0 = lane + 32 * i;
        float val;
        if (e0 < 192) val = ue[e0] * be[e0];
        else if (e0 < 384) val = be[e0 - 192];
        else val = ue[e0 - 384];
        const float4* wr = reinterpret_cast<const float4*>(p1W + (size_t)e0 * 8);
        float4 wa = wr[0], wb = wr[1];
        acc[0] = fmaf(val, wa.x, acc[0]); acc[1] = fmaf(val, wa.y, acc[1]);
        acc[2] = fmaf(val, wa.z, acc[2]); acc[3] = fmaf(val, wa.w, acc[3]);
        acc[4] = fmaf(val, wb.x, acc[4]); acc[5] = fmaf(val, wb.y, acc[5]);
        acc[6] = fmaf(val, wb.z, acc[6]); acc[7] = fmaf(val, wb.w, acc[7]);
    }
#pragma unroll
    for (int o = 16; o; o >>= 1) {
#pragma unroll
        for (int j = 0; j < 8; j++)
            acc[j] += __shfl_xor_sync(0xffffffffu, acc[j], o);
    }
    if (lane == 0) {
        float r = p2b[0];
#pragma unroll
        for (int j = 0; j < 8; j++)
            r += fmaxf(acc[j] + p1b[j], 0.f) * p2W[j];
        out[b] = r;
    }
}

// ---------------------------------------------------------------------------
// Launcher
// ---------------------------------------------------------------------------
extern "C" void kernel_launch(void* const* d_in, const int* in_sizes, int n_in,
                              void* d_out, int out_size)
{
    const float* users_feature   = (const float*)d_in[0];
    const float* items_feature   = (const float*)d_in[1];
    const float* bundles_feature = (const float*)d_in[2];
    const float* Wq    = (const float*)d_in[3];
    const float* Wk    = (const float*)d_in[4];
    const float* Wv    = (const float*)d_in[5];
    const float* Wo    = (const float*)d_in[6];
    const float* W_ub  = (const float*)d_in[7];
    const float* b_ub  = (const float*)d_in[8];
    const float* att_b_w = (const float*)d_in[11];
    const float* p1_W  = (const float*)d_in[13];
    const float* p1_b  = (const float*)d_in[14];
    const float* p2_W  = (const float*)d_in[15];
    const float* p2_b  = (const float*)d_in[16];
    const float* A_i   = (const float*)d_in[17];
    const float* B_i   = (const float*)d_in[18];
    const float* bi_avg = (const float*)d_in[19];
    const float* ui_avg = (const float*)d_in[20];
    const float* ub_avg = (const float*)d_in[21];
    const float* ub_graph = (const float*)d_in[23];
    const int* users   = (const int*)d_in[25];
    const int* bundles = (const int*)d_in[26];

    float* base = nullptr;
    cudaGetSymbolAddress((void**)&base, g_scratch);
    int* needed = nullptr;
    cudaGetSymbolAddress((void**)&needed, g_needed);
    float* it0   = base + OFF_IT0;
    float* q     = base + OFF_Q;
    float* k     = base + OFF_K;
    float* v     = base + OFF_V;
    float* ctx   = base + OFF_CTX;
    float* items = base + OFF_ITEMS;
    float* P     = base + OFF_P;
    float* fub0  = base + OFF_FUB0;
    float* tbuf  = base + OFF_T;
    float* fub   = base + OFF_FUB;
    float* allub = base + OFF_ALLUB;

    // 0. needed-row flags
    flags_zero_kernel<<<36, 256>>>();
    flags_set_kernel<<<16, 256>>>(users, bundles);

    // 1. items0 = relu(A_i@xf) + relu(B_i@xf) + xf
    scan_spmm_kernel<<<384, 256>>>(A_i, I_DIM, items_feature,
                                   B_i, I_DIM, items_feature,
                                   items_feature, nullptr, nullptr,
                                   it0, nullptr, I_DIM);
    // 2. q,k,v (q pre-scaled)
    qkv_kernel<<<192, 256>>>(it0, Wq, Wk, Wv, q, k, v, I_DIM);
    // 3. attention -> ctx
    attn_kernel<<<768, 256>>>(q, k, v, ctx);
    // 4. items = ctx @ Wo
    gemm64_kernel<<<192, 256>>>(ctx, Wo, items, I_DIM);
    // 5. P = relu(bi_avg@items); bundles_f = P + bundles_feature
    scan_spmm_kernel<<<375, 256>>>(bi_avg, I_DIM, items,
                                   nullptr, 0, nullptr,
                                   bundles_feature, nullptr, nullptr,
                                   fub0 + (size_t)U_DIM * 64, P, B_DIM);
    // 6. users_f = relu(ui_avg@items) + relu(ub_avg@bundles_f) + users_feature
    scan_spmm_kernel<<<750, 256>>>(ui_avg, I_DIM, items,
                                   ub_avg, B_DIM, fub0 + (size_t)U_DIM * 64,
                                   users_feature, nullptr, nullptr,
                                   fub0, nullptr, U_DIM);
    // 7. t = fub0 @ W_ub
    gemm64_kernel<<<563, 256>>>(fub0, W_ub, tbuf, UB_DIM);
    // 8. f_ub = relu(ub_graph @ t + b_ub)  -- needed rows only
    scan_spmm_kernel<<<1125, 256>>>(ub_graph, UB_DIM, tbuf,
                                    nullptr, 0, nullptr,
                                    nullptr, b_ub, needed,
                                    fub, nullptr, UB_DIM);
    // 9. att2 fusion (l2norm(P) inline) + all_ub assembly -- needed rows only
    att2_allub_kernel<<<1125, 256>>>(fub0, P, fub, att_b_w, allub);
    // 10. gather + MLP -> out
    final_kernel<<<512, 256>>>(allub, users, bundles, p1_W, p1_b, p2_W, p2_b,
                               (float*)d_out, BATCH);
}